// round 16
// baseline (speedup 1.0000x reference)
#include <cuda_runtime.h>
#include <cuda_fp16.h>
#include <math.h>
#include <stdint.h>

// Problem constants
#define BATCH 2
#define SEQ   2048
#define DIM   1024
#define HEADS 16
#define HD    64
#define MTOT  (BATCH*SEQ)      // 4096

// GEMM tiling: plain fp16 GEMM, K = 1024.
#define TM 128
#define TN 128
#define BK 32
#define NCHUNK (DIM/BK)        // 32
#define STAGES 4
#define RS (BK+8)              // 40 elems = 80 B row stride (conflict-free)
#define STAGE_ELEMS (2*128*RS)
#define STAGE_BYTES (STAGE_ELEMS*2)        // 20480
#define GEMM_SMEM (STAGES*STAGE_BYTES)     // 81920 B -> 2 CTAs/SM
#define QKV_TILES (3 * (DIM/TN) * (MTOT/TM))   // 768

// Scratch (device globals; allocation-free contract)
__device__ __align__(256) __half g_qh[(size_t)MTOT*DIM];
__device__ __align__(256) __half g_kh[(size_t)MTOT*DIM];
__device__ __align__(256) __half g_vh[(size_t)MTOT*DIM];
__device__ __align__(256) float g_kmean[BATCH*HEADS*HD];
__device__ __align__(256) __half g_x1[(size_t)MTOT*DIM];
__device__ __align__(256) __half g_att1[(size_t)MTOT*DIM];
__device__ __align__(256) __half g_wq1[(size_t)DIM*DIM];
__device__ __align__(256) __half g_wk1[(size_t)DIM*DIM];
__device__ __align__(256) __half g_wv1[(size_t)DIM*DIM];
__device__ __align__(256) __half g_wo1[(size_t)DIM*DIM];

// ---------------------------------------------------------------------------
// Non-arch-variant PTX helpers (compute_103-safe)
// ---------------------------------------------------------------------------
__device__ __forceinline__ uint32_t smem_u32(const void* p) {
    uint32_t a;
    asm("{ .reg .u64 t; cvta.to.shared.u64 t, %1; cvt.u32.u64 %0, t; }"
        : "=r"(a) : "l"(p));
    return a;
}
__device__ __forceinline__ void cp16(uint32_t dst, const void* src) {
    asm volatile("cp.async.cg.shared.global [%0], [%1], 16;"
                 :: "r"(dst), "l"(src));
}
#define CP_COMMIT() asm volatile("cp.async.commit_group;" ::: "memory")
#define CP_WAIT2()  asm volatile("cp.async.wait_group 2;" ::: "memory")

__device__ __forceinline__ void ldsm4(uint32_t* d, uint32_t addr) {
    asm volatile("ldmatrix.sync.aligned.m8n8.x4.shared.b16 {%0,%1,%2,%3}, [%4];"
                 : "=r"(d[0]), "=r"(d[1]), "=r"(d[2]), "=r"(d[3]) : "r"(addr));
}

__device__ __forceinline__ void mma_f16(float* c, const uint32_t* a,
                                        const uint32_t* b) {
    asm volatile(
        "mma.sync.aligned.m16n8k16.row.col.f32.f16.f16.f32 "
        "{%0,%1,%2,%3}, {%4,%5,%6,%7}, {%8,%9}, {%0,%1,%2,%3};"
        : "+f"(c[0]), "+f"(c[1]), "+f"(c[2]), "+f"(c[3])
        : "r"(a[0]), "r"(a[1]), "r"(a[2]), "r"(a[3]), "r"(b[0]), "r"(b[1]));
}

__device__ __forceinline__ float4 h4_to_f4(uint2 u) {
    __half2 h0 = *(__half2*)&u.x, h1 = *(__half2*)&u.y;
    float2 f0 = __half22float2(h0), f1 = __half22float2(h1);
    return make_float4(f0.x, f0.y, f1.x, f1.y);
}
__device__ __forceinline__ uint32_t f22h2(float a, float b) {
    __half2 h = __floats2half2_rn(a, b);
    return *(uint32_t*)&h;
}

// ---------------------------------------------------------------------------
// fp16 conversion (no split).
// ---------------------------------------------------------------------------
__global__ __launch_bounds__(256)
void convert_kernel(const float* __restrict__ x,  const float* __restrict__ wq,
                    const float* __restrict__ wk, const float* __restrict__ wv,
                    const float* __restrict__ wo) {
    int rid = blockIdx.x;
    const float* src; __half* dst; int row;
    if      (rid < 4096) { src = x;  dst = g_x1;  row = rid;        }
    else if (rid < 5120) { src = wq; dst = g_wq1; row = rid - 4096; }
    else if (rid < 6144) { src = wk; dst = g_wk1; row = rid - 5120; }
    else if (rid < 7168) { src = wv; dst = g_wv1; row = rid - 6144; }
    else                 { src = wo; dst = g_wo1; row = rid - 7168; }
    int c = threadIdx.x * 4;
    float4 f = *(const float4*)(src + (size_t)row * DIM + c);
    union { __half b[4]; uint2 u; } H;
    H.b[0] = __float2half(f.x); H.b[1] = __float2half(f.y);
    H.b[2] = __float2half(f.z); H.b[3] = __float2half(f.w);
    *(uint2*)(dst + (size_t)row * DIM + c) = H.u;
}

// ---------------------------------------------------------------------------
// Plain fp16 HMMA GEMM tile: C[128x128] panel at (bx, by).
// ---------------------------------------------------------------------------
__device__ __forceinline__ void load_stage(uint32_t stg,
                                           const __half* __restrict__ Ag,
                                           const __half* __restrict__ Bg,
                                           int chunk, int tid) {
    const __half* Ac = Ag + chunk * BK;
    const __half* Bc = Bg + chunk * BK;
#pragma unroll
    for (int i = 0; i < 2; i++) {
        int seg = tid + 256 * i;
        int r = seg >> 2, cs = seg & 3;
        cp16(stg + r * (RS*2) + cs * 16,
             (const char*)(Ac + (size_t)r * DIM) + cs * 16);
    }
#pragma unroll
    for (int i = 0; i < 2; i++) {
        int seg = tid + 256 * i;
        int r = seg >> 2, cs = seg & 3;
        cp16(stg + 128*(RS*2) + r * (RS*2) + cs * 16,
             (const char*)(Bc + (size_t)r * DIM) + cs * 16);
    }
}

template <typename OutT>
__device__ __forceinline__ void mma_gemm_tile(int bx, int by,
                                              const __half* __restrict__ A1,
                                              const __half* __restrict__ B1,
                                              OutT* __restrict__ C) {
    extern __shared__ __align__(128) __half smem[];
    const uint32_t sb = smem_u32(smem);
    const int tid = threadIdx.x;
    const int lane = tid & 31, w = tid >> 5;
    const int wm = w >> 2, wn = w & 3;        // 2 x 4 warp grid
    const int g = lane >> 2, tg = lane & 3;   // epilogue mapping
    const int rowC = by * TM;
    const int colC = bx * TN;
    const __half* Ag = A1 + (size_t)rowC * DIM;
    const __half* Bg = B1 + (size_t)colC * DIM;

    const int arow = wm * 64 + (lane & 15);
    const int acol = (lane >> 4) * 8;
    uint32_t a_rel[4];
#pragma unroll
    for (int mt = 0; mt < 4; mt++)
        a_rel[mt] = (uint32_t)(((arow + mt * 16) * RS + acol) * 2);
    const int brow = wn * 32 + (lane & 7) + ((lane >> 4) << 3);
    const int bcol = ((lane >> 3) & 1) * 8;
    uint32_t b_rel[2];
#pragma unroll
    for (int p = 0; p < 2; p++)
        b_rel[p] = (uint32_t)(((128 + brow + p * 16) * RS + bcol) * 2);

    float acc[4][4][4];
#pragma unroll
    for (int mt = 0; mt < 4; mt++)
#pragma unroll
        for (int nt = 0; nt < 4; nt++)
#pragma unroll
            for (int i = 0; i < 4; i++) acc[mt][nt][i] = 0.f;

#pragma unroll
    for (int s = 0; s < STAGES - 1; s++) {
        load_stage(sb + s * STAGE_BYTES, Ag, Bg, s, tid);
        CP_COMMIT();
    }

    for (int c = 0; c < NCHUNK; c++) {
        CP_WAIT2();
        __syncthreads();
        const uint32_t stg = sb + (uint32_t)(c & 3) * STAGE_BYTES;

        if (c + (STAGES - 1) < NCHUNK)
            load_stage(sb + (uint32_t)((c + STAGES - 1) & 3) * STAGE_BYTES,
                       Ag, Bg, c + STAGES - 1, tid);
        CP_COMMIT();

#pragma unroll
        for (int ks = 0; ks < 2; ks++) {
            const uint32_t ko = (uint32_t)(ks * 16 * 2);
            uint32_t a[4][4], b[2][4];
#pragma unroll
            for (int mt = 0; mt < 4; mt++) ldsm4(a[mt], stg + a_rel[mt] + ko);
#pragma unroll
            for (int p = 0; p < 2; p++)    ldsm4(b[p],  stg + b_rel[p] + ko);
#pragma unroll
            for (int mt = 0; mt < 4; mt++)
#pragma unroll
                for (int nt = 0; nt < 4; nt++)
                    mma_f16(acc[mt][nt], a[mt], &b[nt >> 1][(nt & 1) * 2]);
        }
    }

#pragma unroll
    for (int mt = 0; mt < 4; mt++) {
        const int row = rowC + wm * 64 + mt * 16 + g;
#pragma unroll
        for (int nt = 0; nt < 4; nt++) {
            const int col = colC + wn * 32 + nt * 8 + tg * 2;
            if constexpr (sizeof(OutT) == 4) {
                *(float2*)((float*)C + (size_t)row * DIM + col) =
                    make_float2(acc[mt][nt][0], acc[mt][nt][1]);
                *(float2*)((float*)C + (size_t)(row + 8) * DIM + col) =
                    make_float2(acc[mt][nt][2], acc[mt][nt][3]);
            } else {
                __half2 h0 = __floats2half2_rn(acc[mt][nt][0], acc[mt][nt][1]);
                __half2 h1 = __floats2half2_rn(acc[mt][nt][2], acc[mt][nt][3]);
                *(__half2*)((__half*)C + (size_t)row * DIM + col) = h0;
                *(__half2*)((__half*)C + (size_t)(row + 8) * DIM + col) = h1;
            }
        }
    }
}

// Persistent qkv GEMM: grid = 2*SMs CTAs loop over all 768 tiles.
__global__ __launch_bounds__(256, 2)
void qkv_mma_kernel() {
    for (int tile = blockIdx.x; tile < QKV_TILES; tile += gridDim.x) {
        const int z = tile >> 8;          // 256 tiles per matrix
        const int rem = tile & 255;
        const __half* W = (z == 0) ? g_wq1 : (z == 1) ? g_wk1 : g_wv1;
        __half* C = (z == 0) ? g_qh : (z == 1) ? g_kh : g_vh;
        mma_gemm_tile<__half>(rem & 7, rem >> 3, g_x1, W, C);
        __syncthreads();   // protect stage buffers across tile boundary
    }
}

__global__ __launch_bounds__(256, 2)
void out_mma_kernel(float* __restrict__ out) {
    mma_gemm_tile<float>(blockIdx.x, blockIdx.y, g_att1, g_wo1, out);
}

// ---------------------------------------------------------------------------
// k_mean[b,h,d] = mean_l k[b,h,l,d]   (fp16 k input)
// ---------------------------------------------------------------------------
__global__ __launch_bounds__(256)
void kmean_kernel() {
    __shared__ float red[256];
    const int bh = blockIdx.x;
    const int b = bh >> 4, h = bh & 15;
    const int d = threadIdx.x & 63, p = threadIdx.x >> 6;
    const __half* base = g_kh + (size_t)b * SEQ * DIM + h * HD + d;
    float s = 0.f;
    for (int l = p; l < SEQ; l += 4) s += __half2float(base[(size_t)l * DIM]);
    red[threadIdx.x] = s;
    __syncthreads();
    if (threadIdx.x < 64) {
        float t = red[d] + red[64 + d] + red[128 + d] + red[192 + d];
        g_kmean[bh * HD + d] = t * (1.f / (float)SEQ);
    }
}

// ---------------------------------------------------------------------------
// Fused windowed attention v3b: HMMA for S=QK^T and O=PV with cross-warp
// softmax combination. (Proven in R15; unchanged.)
// ---------------------------------------------------------------------------
#define QH_S 72
#define KH_S 72
#define VT_S 136
#define OR_S 68
#define ATTN_SMEM (64*QH_S*2 + 128*KH_S*2 + 64*VT_S*2 + 64*OR_S*4 + 64*4 + 256*4)

__global__ void __launch_bounds__(256, 2)
attn_kernel(const float* __restrict__ gsep,
            const float* __restrict__ galign,
            const float* __restrict__ gcoh) {
    extern __shared__ __align__(128) char asm_[];
    __half* Qh = (__half*)asm_;                 // [64][QH_S]
    __half* Kh = Qh + 64 * QH_S;                // [128][KH_S]
    __half* Vt = Kh + 128 * KH_S;               // [64 d][VT_S seq]
    float*  Ored = (float*)(Vt + 64 * VT_S);    // [64][OR_S]
    float*  pm = Ored + 64 * OR_S;              // [64]
    float*  rmx = pm + 64;                      // [2][64]
    float*  rsum = rmx + 128;                   // [2][64]

    const int t  = blockIdx.x;
    const int bh = blockIdx.y;
    const int b  = bh >> 4, h = bh & 15;
    const int tid = threadIdx.x;
    const int lane = tid & 31, w = tid >> 5;
    const int wm = w >> 1, wn = w & 1;          // 4 x 2 warp grid
    const int g = lane >> 2, tg = lane & 3;
    const int base = t * 64 - 64;

    const __half* Kg = g_kh + (size_t)b * SEQ * DIM + h * HD;
    const __half* Vg = g_vh + (size_t)b * SEQ * DIM + h * HD;
    const __half* Qg = g_qh + (size_t)b * SEQ * DIM + h * HD;

#pragma unroll
    for (int it = 0; it < 4; it++) {
        int idx = tid + 256 * it;
        int r = idx >> 4, c4 = (idx & 15) * 4;
        *(uint2*)(Qh + r * QH_S + c4) =
            *(const uint2*)(Qg + (size_t)(t * 64 + r) * DIM + c4);
    }
#pragma unroll
    for (int it = 0; it < 8; it++) {
        int idx = tid + 256 * it;
        int r = idx >> 4, c4 = (idx & 15) * 4;
        int j = base + r;
        uint2 u = make_uint2(0u, 0u);
        if (j >= 0) u = *(const uint2*)(Kg + (size_t)j * DIM + c4);
        *(uint2*)(Kh + r * KH_S + c4) = u;
    }
#pragma unroll
    for (int it = 0; it < 8; it++) {
        int idx = tid + 256 * it;
        int n = idx & 127, d0 = (idx >> 7) * 4;
        int j = base + n;
        union { uint2 u; __half v[4]; } V;
        V.u = make_uint2(0u, 0u);
        if (j >= 0) V.u = *(const uint2*)(Vg + (size_t)j * DIM + d0);
        Vt[(d0 + 0) * VT_S + n] = V.v[0];
        Vt[(d0 + 1) * VT_S + n] = V.v[1];
        Vt[(d0 + 2) * VT_S + n] = V.v[2];
        Vt[(d0 + 3) * VT_S + n] = V.v[3];
    }
    __syncthreads();

    if (tid < 64) {
        const float* kmg = g_kmean + bh * HD;
        float s = 0.f;
#pragma unroll
        for (int d4 = 0; d4 < 64; d4 += 4) {
            float4 kk = *(const float4*)(kmg + d4);
            float4 qf = h4_to_f4(*(uint2*)(Qh + tid * QH_S + d4));
            s += qf.x * kk.x + qf.y * kk.y + qf.z * kk.z + qf.w * kk.w;
        }
        pm[tid] = s * 0.125f;
    }

    const uint32_t QhA = smem_u32(Qh), KhA = smem_u32(Kh), VtA = smem_u32(Vt);

    const uint32_t a_rel = (uint32_t)(((wm * 16 + (lane & 15)) * QH_S
                                       + (lane >> 4) * 8) * 2);
    const int brow = (lane & 7) + ((lane >> 4) << 3);
    const int bcol = ((lane >> 3) & 1) * 8;
    uint32_t bS_rel[4], bV_rel[4];
#pragma unroll
    for (int p = 0; p < 4; p++) {
        bS_rel[p] = (uint32_t)(((wn * 64 + p * 16 + brow) * KH_S + bcol) * 2);
        bV_rel[p] = (uint32_t)(((p * 16 + brow) * VT_S + bcol) * 2);
    }

    __syncthreads();

    float acc[8][4];
#pragma unroll
    for (int nt = 0; nt < 8; nt++)
#pragma unroll
        for (int i = 0; i < 4; i++) acc[nt][i] = 0.f;

#pragma unroll
    for (int ks = 0; ks < 4; ks++) {
        uint32_t a[4], bf[4][4];
        ldsm4(a, QhA + a_rel + ks * 32);
#pragma unroll
        for (int p = 0; p < 4; p++) ldsm4(bf[p], KhA + bS_rel[p] + ks * 32);
#pragma unroll
        for (int nt = 0; nt < 8; nt++)
            mma_f16(acc[nt], a, &bf[nt >> 1][(nt & 1) * 2]);
    }

    const float sep = *gsep, alg = *galign, coh = *gcoh;
    float lmx[2], lsum[2];
#pragma unroll
    for (int rh = 0; rh < 2; rh++) {
        const int qi = wm * 16 + g + rh * 8;
        const float mi = pm[qi];
        float mx = -1e30f;
#pragma unroll
        for (int nt = 0; nt < 8; nt++)
#pragma unroll
            for (int j = 0; j < 2; j++) {
                const float s = acc[nt][rh * 2 + j] * 0.125f;
                const int n = wn * 64 + nt * 8 + tg * 2 + j;
                const float sim = 1.f / (1.f + __expf(-s));
                const float v = s + alg * s - sep * sim * sim
                                - coh * fabsf(s - mi);
                const bool ok = (n >= qi + 1) && (n <= qi + 64)
                                && (base + n >= 0);
                acc[nt][rh * 2 + j] = ok ? v : -1e30f;
                mx = fmaxf(mx, acc[nt][rh * 2 + j]);
            }
        mx = fmaxf(mx, __shfl_xor_sync(0xffffffffu, mx, 1));
        mx = fmaxf(mx, __shfl_xor_sync(0xffffffffu, mx, 2));
        float sum = 0.f;
#pragma unroll
        for (int nt = 0; nt < 8; nt++)
#pragma unroll
            for (int j = 0; j < 2; j++) {
                float& e = acc[nt][rh * 2 + j];
                e = (e > -1e29f) ? __expf(e - mx) : 0.f;
                sum += e;
            }
        sum += __shfl_xor_sync(0xffffffffu, sum, 1);
        sum += __shfl_xor_sync(0xffffffffu, sum, 2);
        lmx[rh] = mx;
        lsum[rh] = sum;
        if (tg == 0) { rmx[wn * 64 + qi] = mx; rsum[wn * 64 + qi] = sum; }
    }
    __syncthreads();

#pragma unroll
    for (int rh = 0; rh < 2; rh++) {
        const int qi = wm * 16 + g + rh * 8;
        const float omx = rmx[(1 - wn) * 64 + qi];
        const float osum = rsum[(1 - wn) * 64 + qi];
        const float gm = fmaxf(lmx[rh], omx);
        const float msc = __expf(lmx[rh] - gm);
        const float total = lsum[rh] * msc + osum * __expf(omx - gm);
        const float inv = msc / total;
#pragma unroll
        for (int nt = 0; nt < 8; nt++)
#pragma unroll
            for (int j = 0; j < 2; j++) acc[nt][rh * 2 + j] *= inv;
    }

    float o2[8][4];
#pragma unroll
    for (int dt = 0; dt < 8; dt++)
#pragma unroll
        for (int i = 0; i < 4; i++) o2[dt][i] = 0.f;

#pragma unroll
    for (int ks = 0; ks < 4; ks++) {
        const int t0 = ks * 2, t1 = ks * 2 + 1;
        uint32_t a[4];
        a[0] = f22h2(acc[t0][0], acc[t0][1]);
        a[1] = f22h2(acc[t0][2], acc[t0][3]);
        a[2] = f22h2(acc[t1][0], acc[t1][1]);
        a[3] = f22h2(acc[t1][2], acc[t1][3]);
        uint32_t bf[4][4];
        const uint32_t ko = (uint32_t)((wn * 64 + ks * 16) * 2);
#pragma unroll
        for (int p = 0; p < 4; p++) ldsm4(bf[p], VtA + bV_rel[p] + ko);
#pragma unroll
        for (int dt = 0; dt < 8; dt++)
            mma_f16(o2[dt], a, &bf[dt >> 1][(dt & 1) * 2]);
    }

    if (wn == 1) {
#pragma unroll
        for (int dt = 0; dt < 8; dt++) {
            *(float2*)(Ored + (wm * 16 + g) * OR_S + dt * 8 + tg * 2) =
                make_float2(o2[dt][0], o2[dt][1]);
            *(float2*)(Ored + (wm * 16 + g + 8) * OR_S + dt * 8 + tg * 2) =
                make_float2(o2[dt][2], o2[dt][3]);
        }
    }
    __syncthreads();
    if (wn == 0) {
        const int i0 = t * 64 + wm * 16 + g;
#pragma unroll
        for (int dt = 0; dt < 8; dt++) {
            float2 r0 = *(float2*)(Ored + (wm * 16 + g) * OR_S + dt * 8 + tg * 2);
            float2 r1 = *(float2*)(Ored + (wm * 16 + g + 8) * OR_S + dt * 8 + tg * 2);
            __half2 h0 = __floats2half2_rn(o2[dt][0] + r0.x, o2[dt][1] + r0.y);
            __half2 h1 = __floats2half2_rn(o2[dt][2] + r1.x, o2[dt][3] + r1.y);
            *(__half2*)(g_att1 + ((size_t)b * SEQ + i0) * DIM
                        + h * HD + dt * 8 + tg * 2) = h0;
            *(__half2*)(g_att1 + ((size_t)b * SEQ + i0 + 8) * DIM
                        + h * HD + dt * 8 + tg * 2) = h1;
        }
    }
}

// ---------------------------------------------------------------------------
extern "C" void kernel_launch(void* const* d_in, const int* in_sizes, int n_in,
                              void* d_out, int out_size) {
    const float* x    = (const float*)d_in[0];
    const float* Wq   = (const float*)d_in[1];
    const float* Wk   = (const float*)d_in[2];
    const float* Wv   = (const float*)d_in[3];
    const float* Wo   = (const float*)d_in[4];
    const float* gsep = (const float*)d_in[5];
    const float* galn = (const float*)d_in[6];
    const float* gcoh = (const float*)d_in[7];
    float* out = (float*)d_out;

    static int nsm = -1;
    if (nsm < 0) {
        cudaDeviceGetAttribute(&nsm, cudaDevAttrMultiProcessorCount, 0);
        if (nsm <= 0) nsm = 148;
    }

    cudaFuncSetAttribute(qkv_mma_kernel,
                         cudaFuncAttributeMaxDynamicSharedMemorySize, GEMM_SMEM);
    cudaFuncSetAttribute(out_mma_kernel,
                         cudaFuncAttributeMaxDynamicSharedMemorySize, GEMM_SMEM);
    cudaFuncSetAttribute(attn_kernel,
                         cudaFuncAttributeMaxDynamicSharedMemorySize, ATTN_SMEM);

    convert_kernel<<<8192, 256>>>(x, Wq, Wk, Wv, Wo);

    qkv_mma_kernel<<<2 * nsm, 256, GEMM_SMEM>>>();

    kmean_kernel<<<BATCH * HEADS, 256>>>();

    dim3 gatt(SEQ / 64, BATCH * HEADS);
    attn_kernel<<<gatt, 256, ATTN_SMEM>>>(gsep, galn, gcoh);

    dim3 gout(DIM / TN, MTOT / TM);
    out_mma_kernel<<<gout, 256, GEMM_SMEM>>>(out);
}

// round 17
// speedup vs baseline: 1.0532x; 1.0532x over previous
#include <cuda_runtime.h>
#include <cuda_fp16.h>
#include <math.h>
#include <stdint.h>

// Problem constants
#define BATCH 2
#define SEQ   2048
#define DIM   1024
#define HEADS 16
#define HD    64
#define MTOT  (BATCH*SEQ)      // 4096

// GEMM tiling: plain fp16 GEMM, K = 1024.
#define TM 128
#define TN 128
#define BK 32
#define NCHUNK (DIM/BK)        // 32
#define STAGES 4
#define RS (BK+8)              // 40 elems = 80 B row stride (conflict-free)
#define STAGE_ELEMS (2*128*RS)
#define STAGE_BYTES (STAGE_ELEMS*2)        // 20480
#define GEMM_SMEM (STAGES*STAGE_BYTES)     // 81920 B -> 2 CTAs/SM

// Scratch (device globals; allocation-free contract)
__device__ __align__(256) __half g_qh[(size_t)MTOT*DIM];
__device__ __align__(256) __half g_kh[(size_t)MTOT*DIM];
__device__ __align__(256) __half g_vh[(size_t)MTOT*DIM];
__device__ __align__(256) float g_kmean[BATCH*HEADS*HD];
__device__ __align__(256) __half g_x1[(size_t)MTOT*DIM];
__device__ __align__(256) __half g_att1[(size_t)MTOT*DIM];
__device__ __align__(256) __half g_wq1[(size_t)DIM*DIM];
__device__ __align__(256) __half g_wk1[(size_t)DIM*DIM];
__device__ __align__(256) __half g_wv1[(size_t)DIM*DIM];
__device__ __align__(256) __half g_wo1[(size_t)DIM*DIM];

// ---------------------------------------------------------------------------
// Non-arch-variant PTX helpers (compute_103-safe)
// ---------------------------------------------------------------------------
__device__ __forceinline__ uint32_t smem_u32(const void* p) {
    uint32_t a;
    asm("{ .reg .u64 t; cvta.to.shared.u64 t, %1; cvt.u32.u64 %0, t; }"
        : "=r"(a) : "l"(p));
    return a;
}
__device__ __forceinline__ void cp16(uint32_t dst, const void* src) {
    asm volatile("cp.async.cg.shared.global [%0], [%1], 16;"
                 :: "r"(dst), "l"(src));
}
#define CP_COMMIT() asm volatile("cp.async.commit_group;" ::: "memory")
#define CP_WAIT2()  asm volatile("cp.async.wait_group 2;" ::: "memory")

__device__ __forceinline__ void ldsm4(uint32_t* d, uint32_t addr) {
    asm volatile("ldmatrix.sync.aligned.m8n8.x4.shared.b16 {%0,%1,%2,%3}, [%4];"
                 : "=r"(d[0]), "=r"(d[1]), "=r"(d[2]), "=r"(d[3]) : "r"(addr));
}

__device__ __forceinline__ void mma_f16(float* c, const uint32_t* a,
                                        const uint32_t* b) {
    asm volatile(
        "mma.sync.aligned.m16n8k16.row.col.f32.f16.f16.f32 "
        "{%0,%1,%2,%3}, {%4,%5,%6,%7}, {%8,%9}, {%0,%1,%2,%3};"
        : "+f"(c[0]), "+f"(c[1]), "+f"(c[2]), "+f"(c[3])
        : "r"(a[0]), "r"(a[1]), "r"(a[2]), "r"(a[3]), "r"(b[0]), "r"(b[1]));
}

__device__ __forceinline__ float4 h4_to_f4(uint2 u) {
    __half2 h0 = *(__half2*)&u.x, h1 = *(__half2*)&u.y;
    float2 f0 = __half22float2(h0), f1 = __half22float2(h1);
    return make_float4(f0.x, f0.y, f1.x, f1.y);
}

// ---------------------------------------------------------------------------
// fp16 conversion (no split).
// ---------------------------------------------------------------------------
__global__ __launch_bounds__(256)
void convert_kernel(const float* __restrict__ x,  const float* __restrict__ wq,
                    const float* __restrict__ wk, const float* __restrict__ wv,
                    const float* __restrict__ wo) {
    int rid = blockIdx.x;
    const float* src; __half* dst; int row;
    if      (rid < 4096) { src = x;  dst = g_x1;  row = rid;        }
    else if (rid < 5120) { src = wq; dst = g_wq1; row = rid - 4096; }
    else if (rid < 6144) { src = wk; dst = g_wk1; row = rid - 5120; }
    else if (rid < 7168) { src = wv; dst = g_wv1; row = rid - 6144; }
    else                 { src = wo; dst = g_wo1; row = rid - 7168; }
    int c = threadIdx.x * 4;
    float4 f = *(const float4*)(src + (size_t)row * DIM + c);
    union { __half b[4]; uint2 u; } H;
    H.b[0] = __float2half(f.x); H.b[1] = __float2half(f.y);
    H.b[2] = __float2half(f.z); H.b[3] = __float2half(f.w);
    *(uint2*)(dst + (size_t)row * DIM + c) = H.u;
}

// ---------------------------------------------------------------------------
// Plain fp16 HMMA GEMM: C[4096,1024] = A[4096,1024] @ B[1024,1024]^T (f32 acc)
// ---------------------------------------------------------------------------
__device__ __forceinline__ void load_stage(uint32_t stg,
                                           const __half* __restrict__ Ag,
                                           const __half* __restrict__ Bg,
                                           int chunk, int tid) {
    const __half* Ac = Ag + chunk * BK;
    const __half* Bc = Bg + chunk * BK;
#pragma unroll
    for (int i = 0; i < 2; i++) {
        int seg = tid + 256 * i;
        int r = seg >> 2, cs = seg & 3;
        cp16(stg + r * (RS*2) + cs * 16,
             (const char*)(Ac + (size_t)r * DIM) + cs * 16);
    }
#pragma unroll
    for (int i = 0; i < 2; i++) {
        int seg = tid + 256 * i;
        int r = seg >> 2, cs = seg & 3;
        cp16(stg + 128*(RS*2) + r * (RS*2) + cs * 16,
             (const char*)(Bc + (size_t)r * DIM) + cs * 16);
    }
}

template <typename OutT>
__device__ __forceinline__ void mma_gemm(const __half* __restrict__ A1,
                                         const __half* __restrict__ B1,
                                         OutT* __restrict__ C) {
    extern __shared__ __align__(128) __half smem[];
    const uint32_t sb = smem_u32(smem);
    const int tid = threadIdx.x;
    const int lane = tid & 31, w = tid >> 5;
    const int wm = w >> 2, wn = w & 3;        // 2 x 4 warp grid
    const int g = lane >> 2, tg = lane & 3;   // epilogue mapping
    const int rowC = blockIdx.y * TM;
    const int colC = blockIdx.x * TN;
    const __half* Ag = A1 + (size_t)rowC * DIM;
    const __half* Bg = B1 + (size_t)colC * DIM;

    const int arow = wm * 64 + (lane & 15);
    const int acol = (lane >> 4) * 8;
    uint32_t a_rel[4];
#pragma unroll
    for (int mt = 0; mt < 4; mt++)
        a_rel[mt] = (uint32_t)(((arow + mt * 16) * RS + acol) * 2);
    const int brow = wn * 32 + (lane & 7) + ((lane >> 4) << 3);
    const int bcol = ((lane >> 3) & 1) * 8;
    uint32_t b_rel[2];
#pragma unroll
    for (int p = 0; p < 2; p++)
        b_rel[p] = (uint32_t)(((128 + brow + p * 16) * RS + bcol) * 2);

    float acc[4][4][4];
#pragma unroll
    for (int mt = 0; mt < 4; mt++)
#pragma unroll
        for (int nt = 0; nt < 4; nt++)
#pragma unroll
            for (int i = 0; i < 4; i++) acc[mt][nt][i] = 0.f;

#pragma unroll
    for (int s = 0; s < STAGES - 1; s++) {
        load_stage(sb + s * STAGE_BYTES, Ag, Bg, s, tid);
        CP_COMMIT();
    }

    for (int c = 0; c < NCHUNK; c++) {
        CP_WAIT2();
        __syncthreads();
        const uint32_t stg = sb + (uint32_t)(c & 3) * STAGE_BYTES;

        if (c + (STAGES - 1) < NCHUNK)
            load_stage(sb + (uint32_t)((c + STAGES - 1) & 3) * STAGE_BYTES,
                       Ag, Bg, c + STAGES - 1, tid);
        CP_COMMIT();

#pragma unroll
        for (int ks = 0; ks < 2; ks++) {
            const uint32_t ko = (uint32_t)(ks * 16 * 2);
            uint32_t a[4][4], b[2][4];
#pragma unroll
            for (int mt = 0; mt < 4; mt++) ldsm4(a[mt], stg + a_rel[mt] + ko);
#pragma unroll
            for (int p = 0; p < 2; p++)    ldsm4(b[p],  stg + b_rel[p] + ko);
#pragma unroll
            for (int mt = 0; mt < 4; mt++)
#pragma unroll
                for (int nt = 0; nt < 4; nt++)
                    mma_f16(acc[mt][nt], a[mt], &b[nt >> 1][(nt & 1) * 2]);
        }
    }

#pragma unroll
    for (int mt = 0; mt < 4; mt++) {
        const int row = rowC + wm * 64 + mt * 16 + g;
#pragma unroll
        for (int nt = 0; nt < 4; nt++) {
            const int col = colC + wn * 32 + nt * 8 + tg * 2;
            if constexpr (sizeof(OutT) == 4) {
                *(float2*)((float*)C + (size_t)row * DIM + col) =
                    make_float2(acc[mt][nt][0], acc[mt][nt][1]);
                *(float2*)((float*)C + (size_t)(row + 8) * DIM + col) =
                    make_float2(acc[mt][nt][2], acc[mt][nt][3]);
            } else {
                __half2 h0 = __floats2half2_rn(acc[mt][nt][0], acc[mt][nt][1]);
                __half2 h1 = __floats2half2_rn(acc[mt][nt][2], acc[mt][nt][3]);
                *(__half2*)((__half*)C + (size_t)row * DIM + col) = h0;
                *(__half2*)((__half*)C + (size_t)(row + 8) * DIM + col) = h1;
            }
        }
    }
}

__global__ __launch_bounds__(256, 2)
void qkv_mma_kernel() {
    const __half* W = (blockIdx.z == 0) ? g_wq1
                    : (blockIdx.z == 1) ? g_wk1 : g_wv1;
    __half* C = (blockIdx.z == 0) ? g_qh : (blockIdx.z == 1) ? g_kh : g_vh;
    mma_gemm<__half>(g_x1, W, C);
}

__global__ __launch_bounds__(256, 2)
void out_mma_kernel(float* __restrict__ out) {
    mma_gemm<float>(g_att1, g_wo1, out);
}

// ---------------------------------------------------------------------------
// k_mean[b,h,d] = mean_l k[b,h,l,d]   (fp16 k input)
// ---------------------------------------------------------------------------
__global__ __launch_bounds__(256)
void kmean_kernel() {
    __shared__ float red[256];
    const int bh = blockIdx.x;
    const int b = bh >> 4, h = bh & 15;
    const int d = threadIdx.x & 63, p = threadIdx.x >> 6;
    const __half* base = g_kh + (size_t)b * SEQ * DIM + h * HD + d;
    float s = 0.f;
    for (int l = p; l < SEQ; l += 4) s += __half2float(base[(size_t)l * DIM]);
    red[threadIdx.x] = s;
    __syncthreads();
    if (threadIdx.x < 64) {
        float t = red[d] + red[64 + d] + red[128 + d] + red[192 + d];
        g_kmean[bh * HD + d] = t * (1.f / (float)SEQ);
    }
}

// ---------------------------------------------------------------------------
// Fused windowed attention v4: HMMA S and PV, P spilled to smem as fp16
// (reusing dead Kh region). PV = per-warp m16 x d32 x k128, no cross-warp
// reduction. 46.3 KB smem -> 3 CTAs/SM.
// ---------------------------------------------------------------------------
#define QH_S 72
#define KH_S 72     // Kh region (18432 B) reused for Ps (64 x PS_S = 17408 B)
#define PS_S 136
#define VT_S 136
#define ATTN_SMEM (64*QH_S*2 + 128*KH_S*2 + 64*VT_S*2 + 64*4 + 256*4)  // 46336

__global__ void __launch_bounds__(256, 3)
attn_kernel(const float* __restrict__ gsep,
            const float* __restrict__ galign,
            const float* __restrict__ gcoh) {
    extern __shared__ __align__(128) char asm_[];
    __half* Qh = (__half*)asm_;                 // [64][QH_S]
    __half* Kh = Qh + 64 * QH_S;                // [128][KH_S]; later Ps[64][PS_S]
    __half* Vt = Kh + 128 * KH_S;               // [64 d][VT_S seq]
    float*  pm = (float*)(Vt + 64 * VT_S);      // [64]
    float*  rmx = pm + 64;                      // [2][64]
    float*  rsum = rmx + 128;                   // [2][64]

    const int t  = blockIdx.x;
    const int bh = blockIdx.y;
    const int b  = bh >> 4, h = bh & 15;
    const int tid = threadIdx.x;
    const int lane = tid & 31, w = tid >> 5;
    const int wm = w >> 1, wn = w & 1;          // 4 x 2 warp grid (S phase)
    const int wd = wn;                          // PV phase: d-half selector
    const int g = lane >> 2, tg = lane & 3;
    const int base = t * 64 - 64;

    const __half* Kg = g_kh + (size_t)b * SEQ * DIM + h * HD;
    const __half* Vg = g_vh + (size_t)b * SEQ * DIM + h * HD;
    const __half* Qg = g_qh + (size_t)b * SEQ * DIM + h * HD;

    // Stage Q
#pragma unroll
    for (int it = 0; it < 4; it++) {
        int idx = tid + 256 * it;
        int r = idx >> 4, c4 = (idx & 15) * 4;
        *(uint2*)(Qh + r * QH_S + c4) =
            *(const uint2*)(Qg + (size_t)(t * 64 + r) * DIM + c4);
    }
    // Stage K
#pragma unroll
    for (int it = 0; it < 8; it++) {
        int idx = tid + 256 * it;
        int r = idx >> 4, c4 = (idx & 15) * 4;
        int j = base + r;
        uint2 u = make_uint2(0u, 0u);
        if (j >= 0) u = *(const uint2*)(Kg + (size_t)j * DIM + c4);
        *(uint2*)(Kh + r * KH_S + c4) = u;
    }
    // Stage V transposed
#pragma unroll
    for (int it = 0; it < 8; it++) {
        int idx = tid + 256 * it;
        int n = idx & 127, d0 = (idx >> 7) * 4;
        int j = base + n;
        union { uint2 u; __half v[4]; } V;
        V.u = make_uint2(0u, 0u);
        if (j >= 0) V.u = *(const uint2*)(Vg + (size_t)j * DIM + d0);
        Vt[(d0 + 0) * VT_S + n] = V.v[0];
        Vt[(d0 + 1) * VT_S + n] = V.v[1];
        Vt[(d0 + 2) * VT_S + n] = V.v[2];
        Vt[(d0 + 3) * VT_S + n] = V.v[3];
    }
    __syncthreads();

    // pm[qi] = (q . k_mean) / 8
    if (tid < 64) {
        const float* kmg = g_kmean + bh * HD;
        float s = 0.f;
#pragma unroll
        for (int d4 = 0; d4 < 64; d4 += 4) {
            float4 kk = *(const float4*)(kmg + d4);
            float4 qf = h4_to_f4(*(uint2*)(Qh + tid * QH_S + d4));
            s += qf.x * kk.x + qf.y * kk.y + qf.z * kk.z + qf.w * kk.w;
        }
        pm[tid] = s * 0.125f;
    }

    const uint32_t QhA = smem_u32(Qh), KhA = smem_u32(Kh), VtA = smem_u32(Vt);

    const uint32_t a_rel = (uint32_t)(((wm * 16 + (lane & 15)) * QH_S
                                       + (lane >> 4) * 8) * 2);
    const int brow = (lane & 7) + ((lane >> 4) << 3);
    const int bcol = ((lane >> 3) & 1) * 8;
    uint32_t bS_rel[4];
#pragma unroll
    for (int p = 0; p < 4; p++)
        bS_rel[p] = (uint32_t)(((wn * 64 + p * 16 + brow) * KH_S + bcol) * 2);
    uint32_t bV_rel[2];
#pragma unroll
    for (int p = 0; p < 2; p++)
        bV_rel[p] = (uint32_t)(((wd * 32 + p * 16 + brow) * VT_S + bcol) * 2);
    const uint32_t aP_rel = (uint32_t)(((wm * 16 + (lane & 15)) * PS_S
                                        + (lane >> 4) * 8) * 2);

    __syncthreads();

    // ---- S = Q K^T : per warp m16 x n64, k=64 ----
    float acc[8][4];
#pragma unroll
    for (int nt = 0; nt < 8; nt++)
#pragma unroll
        for (int i = 0; i < 4; i++) acc[nt][i] = 0.f;

#pragma unroll
    for (int ks = 0; ks < 4; ks++) {
        uint32_t a[4], bf[4][4];
        ldsm4(a, QhA + a_rel + ks * 32);
#pragma unroll
        for (int p = 0; p < 4; p++) ldsm4(bf[p], KhA + bS_rel[p] + ks * 32);
#pragma unroll
        for (int nt = 0; nt < 8; nt++)
            mma_f16(acc[nt], a, &bf[nt >> 1][(nt & 1) * 2]);
    }

    // ---- Reynolds + mask + local softmax stats (per wn half-row) ----
    const float sep = *gsep, alg = *galign, coh = *gcoh;
    float lmx[2], lsum[2];
#pragma unroll
    for (int rh = 0; rh < 2; rh++) {
        const int qi = wm * 16 + g + rh * 8;
        const float mi = pm[qi];
        float mx = -1e30f;
#pragma unroll
        for (int nt = 0; nt < 8; nt++)
#pragma unroll
            for (int j = 0; j < 2; j++) {
                const float s = acc[nt][rh * 2 + j] * 0.125f;
                const int n = wn * 64 + nt * 8 + tg * 2 + j;
                const float sim = 1.f / (1.f + __expf(-s));
                const float v = s + alg * s - sep * sim * sim
                                - coh * fabsf(s - mi);
                const bool ok = (n >= qi + 1) && (n <= qi + 64)
                                && (base + n >= 0);
                acc[nt][rh * 2 + j] = ok ? v : -1e30f;
                mx = fmaxf(mx, acc[nt][rh * 2 + j]);
            }
        mx = fmaxf(mx, __shfl_xor_sync(0xffffffffu, mx, 1));
        mx = fmaxf(mx, __shfl_xor_sync(0xffffffffu, mx, 2));
        float sum = 0.f;
#pragma unroll
        for (int nt = 0; nt < 8; nt++)
#pragma unroll
            for (int j = 0; j < 2; j++) {
                float& e = acc[nt][rh * 2 + j];
                e = (e > -1e29f) ? __expf(e - mx) : 0.f;
                sum += e;
            }
        sum += __shfl_xor_sync(0xffffffffu, sum, 1);
        sum += __shfl_xor_sync(0xffffffffu, sum, 2);
        lmx[rh] = mx;
        lsum[rh] = sum;
        if (tg == 0) { rmx[wn * 64 + qi] = mx; rsum[wn * 64 + qi] = sum; }
    }
    __syncthreads();   // stats visible; also: all Kh ldsm reads complete

    // ---- Combine with partner warp's stats; write P (fp16) into Kh region ----
    __half* Ps = Kh;
#pragma unroll
    for (int rh = 0; rh < 2; rh++) {
        const int qi = wm * 16 + g + rh * 8;
        const float omx = rmx[(1 - wn) * 64 + qi];
        const float osum = rsum[(1 - wn) * 64 + qi];
        const float gm = fmaxf(lmx[rh], omx);
        const float msc = __expf(lmx[rh] - gm);
        const float total = lsum[rh] * msc + osum * __expf(omx - gm);
        const float inv = msc / total;
#pragma unroll
        for (int nt = 0; nt < 8; nt++) {
            const int n = wn * 64 + nt * 8 + tg * 2;
            *(__half2*)(Ps + qi * PS_S + n) =
                __floats2half2_rn(acc[nt][rh * 2] * inv,
                                  acc[nt][rh * 2 + 1] * inv);
        }
    }
    __syncthreads();

    // ---- O = P V : per warp m16 x d32 x k128 (full seq reduction) ----
    const uint32_t PsA = KhA;
    float o2[4][4];
#pragma unroll
    for (int dt = 0; dt < 4; dt++)
#pragma unroll
        for (int i = 0; i < 4; i++) o2[dt][i] = 0.f;

#pragma unroll
    for (int ks = 0; ks < 8; ks++) {
        uint32_t a[4], bf[2][4];
        ldsm4(a, PsA + aP_rel + ks * 32);
#pragma unroll
        for (int p = 0; p < 2; p++) ldsm4(bf[p], VtA + bV_rel[p] + ks * 32);
#pragma unroll
        for (int dt = 0; dt < 4; dt++)
            mma_f16(o2[dt], a, &bf[dt >> 1][(dt & 1) * 2]);
    }

    // ---- Direct fp16 output (each warp owns distinct m16 x d32 block) ----
    const int i0 = t * 64 + wm * 16 + g;
#pragma unroll
    for (int dt = 0; dt < 4; dt++) {
        const int col = h * HD + wd * 32 + dt * 8 + tg * 2;
        *(__half2*)(g_att1 + ((size_t)b * SEQ + i0) * DIM + col) =
            __floats2half2_rn(o2[dt][0], o2[dt][1]);
        *(__half2*)(g_att1 + ((size_t)b * SEQ + i0 + 8) * DIM + col) =
            __floats2half2_rn(o2[dt][2], o2[dt][3]);
    }
}

// ---------------------------------------------------------------------------
extern "C" void kernel_launch(void* const* d_in, const int* in_sizes, int n_in,
                              void* d_out, int out_size) {
    const float* x    = (const float*)d_in[0];
    const float* Wq   = (const float*)d_in[1];
    const float* Wk   = (const float*)d_in[2];
    const float* Wv   = (const float*)d_in[3];
    const float* Wo   = (const float*)d_in[4];
    const float* gsep = (const float*)d_in[5];
    const float* galn = (const float*)d_in[6];
    const float* gcoh = (const float*)d_in[7];
    float* out = (float*)d_out;

    cudaFuncSetAttribute(qkv_mma_kernel,
                         cudaFuncAttributeMaxDynamicSharedMemorySize, GEMM_SMEM);
    cudaFuncSetAttribute(out_mma_kernel,
                         cudaFuncAttributeMaxDynamicSharedMemorySize, GEMM_SMEM);
    cudaFuncSetAttribute(attn_kernel,
                         cudaFuncAttributeMaxDynamicSharedMemorySize, ATTN_SMEM);

    convert_kernel<<<8192, 256>>>(x, Wq, Wk, Wv, Wo);

    dim3 gqkv(DIM / TN, MTOT / TM, 3);
    qkv_mma_kernel<<<gqkv, 256, GEMM_SMEM>>>();

    kmean_kernel<<<BATCH * HEADS, 256>>>();

    dim3 gatt(SEQ / 64, BATCH * HEADS);
    attn_kernel<<<gatt, 256, ATTN_SMEM>>>(gsep, galn, gcoh);

    dim3 gout(DIM / TN, MTOT / TM);
    out_mma_kernel<<<gout, 256, GEMM_SMEM>>>(out);
}